// round 17
// baseline (speedup 1.0000x reference)
#include <cuda_runtime.h>
#include <cuda_bf16.h>
#include <cstdint>

// Shapes: x [4,2048,1024] f32, W [1024,3072] f32, b [3072] f32
// out [4,16,2048,64] f32 = scale * Q (K^T V),  scale = 32
#define M_TOT 8192
#define K_DIM 1024
#define N_TOT 3072
#define BH    64
#define SEQ   2048
#define HD    64
#define NSPLIT 8

// ---- stage-1 geometry ----
#define TBM 256
#define TBN 256
#define CHUNK 64
#define CPT 48
#define NTILES 3
#define A_TILE 32768
#define B_TILE 32768
#define A_RING 3
#define B_RING 4
#define QKV_SMEM (1024 + 1024 + A_RING * A_TILE + B_RING * B_TILE)  // 231424
#define IDESC_BF16 0x08400490u

// stage-2/4 smem geometry (bf16 planes, padded rows: 72 cols = 144B stride)
#define PLANE64 (64 * 72 * 2)            // 9216 B
#define KTV_SMEM (2 * 4 * PLANE64)       // 73728 B
#define OUT_SMEM (2 * 128 * 72 * 2 + 2 * PLANE64)  // 55296 B

// fallback tile params
#define GBK 32
#define APAD 8

#if defined(__CUDA_ARCH__) && (defined(__CUDA_ARCH_FEAT_SM103_ALL) || \
    defined(__CUDA_ARCH_FEAT_SM100_ALL) || defined(__CUDA_ARCH_SPECIFIC__))
#define USE_TC 1
#else
#define USE_TC 0
#endif

// Scratch (device globals; no runtime allocation allowed)
__device__ __nv_bfloat16 g_Xh[(size_t)M_TOT * K_DIM];
__device__ __nv_bfloat16 g_Xl[(size_t)M_TOT * K_DIM];
__device__ __nv_bfloat16 g_Wh[(size_t)N_TOT * K_DIM];
__device__ __nv_bfloat16 g_Wl[(size_t)N_TOT * K_DIM];
__device__ float g_Q[BH * SEQ * HD];                 // [bh][n][d]
__device__ float g_Kt[BH * HD * SEQ];                // [bh][d][n]
__device__ float g_Vt[BH * HD * SEQ];                // [bh][d][n]
__device__ float g_KtVp[BH * NSPLIT * HD * HD];
__device__ float g_KtV[BH * HD * HD];                // [e][d], scale folded

// ---------------------------------------------------------------------------
// common helpers
// ---------------------------------------------------------------------------
__device__ __forceinline__ void split2(float a, float b, uint32_t& hi, uint32_t& lo) {
    __nv_bfloat16 ah = __float2bfloat16_rn(a);
    __nv_bfloat16 bh = __float2bfloat16_rn(b);
    __nv_bfloat16 al = __float2bfloat16_rn(a - __bfloat162float(ah));
    __nv_bfloat16 bl = __float2bfloat16_rn(b - __bfloat162float(bh));
    hi = (uint32_t)(*reinterpret_cast<uint16_t*>(&ah)) |
         ((uint32_t)(*reinterpret_cast<uint16_t*>(&bh)) << 16);
    lo = (uint32_t)(*reinterpret_cast<uint16_t*>(&al)) |
         ((uint32_t)(*reinterpret_cast<uint16_t*>(&bl)) << 16);
}

__device__ __forceinline__ void cp16s(uint32_t smem_addr, const void* gmem) {
    asm volatile("cp.async.cg.shared.global [%0], [%1], 16;" :: "r"(smem_addr), "l"(gmem));
}

__device__ __forceinline__ void mma_bf16(float* c, const uint32_t* a, const uint32_t* b) {
    asm volatile(
        "mma.sync.aligned.m16n8k16.row.col.f32.bf16.bf16.f32 "
        "{%0,%1,%2,%3}, {%4,%5,%6,%7}, {%8,%9}, {%0,%1,%2,%3};"
        : "+f"(c[0]), "+f"(c[1]), "+f"(c[2]), "+f"(c[3])
        : "r"(a[0]), "r"(a[1]), "r"(a[2]), "r"(a[3]), "r"(b[0]), "r"(b[1]));
}
__device__ __forceinline__ void ldsm_x4(uint32_t* r, const void* p) {
    uint32_t a = (uint32_t)__cvta_generic_to_shared(p);
    asm volatile("ldmatrix.sync.aligned.m8n8.x4.shared.b16 {%0,%1,%2,%3}, [%4];"
                 : "=r"(r[0]), "=r"(r[1]), "=r"(r[2]), "=r"(r[3]) : "r"(a));
}

#if USE_TC
__device__ __forceinline__ uint32_t elect_one_pred() {
    uint32_t pred;
    asm volatile("{\n\t.reg .pred p;\n\telect.sync _|p, 0xFFFFFFFF;\n\t"
                 "selp.b32 %0, 1, 0, p;\n\t}" : "=r"(pred));
    return pred;
}
static constexpr uint64_t DESC_BASE_SW128 =
    (uint64_t(2) << 61) | (uint64_t(1) << 46) | (uint64_t(64) << 32) | (uint64_t(1) << 16);
__device__ __forceinline__ uint64_t make_desc(uint32_t addr) {
    return DESC_BASE_SW128 | ((uint64_t)(addr >> 4) & 0x3FFF);
}
__device__ __forceinline__ void mma_f16_ss(uint32_t d, uint64_t ad, uint64_t bd,
                                           uint32_t idesc, uint32_t en) {
    asm volatile(
        "{\n\t.reg .pred p;\n\tsetp.ne.u32 p, %5, 0;\n\t"
        "tcgen05.mma.cta_group::1.kind::f16 [%0], %1, %2, %3, {%4,%4,%4,%4}, p;\n\t}"
        :: "r"(d), "l"(ad), "l"(bd), "r"(idesc), "r"(0u), "r"(en) : "memory");
}
__device__ __forceinline__ void mbar_init(uint32_t a, uint32_t cnt) {
    asm volatile("mbarrier.init.shared.b64 [%0], %1;" :: "r"(a), "r"(cnt) : "memory");
}
__device__ __forceinline__ void mbar_wait(uint32_t a, uint32_t parity) {
    asm volatile(
        "{\n\t.reg .pred P;\n\tLAB_%=:\n\t"
        "mbarrier.try_wait.parity.acquire.cta.shared::cta.b64 P, [%0], %1;\n\t"
        "@!P bra LAB_%=;\n\t}" :: "r"(a), "r"(parity) : "memory");
}
__device__ __forceinline__ void tc_commit(uint32_t mbar) {
    asm volatile(
        "tcgen05.commit.cta_group::1.mbarrier::arrive::one.shared::cluster.b64 [%0];"
        :: "r"(mbar) : "memory");
}
#define LDTM_X32(r, a)                                                         \
    asm volatile("tcgen05.ld.sync.aligned.32x32b.x32.b32 "                     \
        "{%0,%1,%2,%3,%4,%5,%6,%7,%8,%9,%10,%11,%12,%13,%14,%15,"              \
        "%16,%17,%18,%19,%20,%21,%22,%23,%24,%25,%26,%27,%28,%29,%30,%31},"    \
        "[%32];"                                                               \
        : "=r"((r)[0]),"=r"((r)[1]),"=r"((r)[2]),"=r"((r)[3]),                 \
          "=r"((r)[4]),"=r"((r)[5]),"=r"((r)[6]),"=r"((r)[7]),                 \
          "=r"((r)[8]),"=r"((r)[9]),"=r"((r)[10]),"=r"((r)[11]),               \
          "=r"((r)[12]),"=r"((r)[13]),"=r"((r)[14]),"=r"((r)[15]),             \
          "=r"((r)[16]),"=r"((r)[17]),"=r"((r)[18]),"=r"((r)[19]),             \
          "=r"((r)[20]),"=r"((r)[21]),"=r"((r)[22]),"=r"((r)[23]),             \
          "=r"((r)[24]),"=r"((r)[25]),"=r"((r)[26]),"=r"((r)[27]),             \
          "=r"((r)[28]),"=r"((r)[29]),"=r"((r)[30]),"=r"((r)[31])              \
        : "r"(a))
#endif

// ---------------------------------------------------------------------------
// Precompute: x -> Xh/Xl bf16
// ---------------------------------------------------------------------------
__global__ __launch_bounds__(256) void split_x(const float* __restrict__ x) {
    int i = blockIdx.x * 256 + threadIdx.x;
    int m = i >> 8, k4 = (i & 255) << 2;
    float4 v = *(const float4*)&x[(size_t)m * K_DIM + k4];
    uint32_t h01, l01, h23, l23;
    split2(v.x, v.y, h01, l01);
    split2(v.z, v.w, h23, l23);
    size_t base = (size_t)m * K_DIM + k4;
    *(uint2*)&g_Xh[base] = make_uint2(h01, h23);
    *(uint2*)&g_Xl[base] = make_uint2(l01, l23);
}

// ---------------------------------------------------------------------------
// Precompute: W -> Wh/Wl bf16 (transposed)
// ---------------------------------------------------------------------------
__global__ __launch_bounds__(256) void split_w(const float* __restrict__ W) {
    __shared__ float ts[32][33];
    const int k0 = blockIdx.x * 32, n0 = blockIdx.y * 32;
    const int r = threadIdx.x >> 5, c = threadIdx.x & 31;
#pragma unroll
    for (int i = 0; i < 4; i++)
        ts[r + 8 * i][c] = W[(size_t)(k0 + r + 8 * i) * N_TOT + n0 + c];
    __syncthreads();
#pragma unroll
    for (int i = 0; i < 4; i++) {
        int n = n0 + r + 8 * i;
        float f = ts[c][r + 8 * i];
        __nv_bfloat16 hb = __float2bfloat16_rn(f);
        __nv_bfloat16 lb = __float2bfloat16_rn(f - __bfloat162float(hb));
        size_t base = (size_t)n * K_DIM + k0 + c;
        g_Wh[base] = hb;
        g_Wl[base] = lb;
    }
}

// ---------------------------------------------------------------------------
// Stage 1: persistent tcgen05 GEMM. Epilogue writes Q [bh][n][d] (via
// transpose) and K/V TRANSPOSED [bh][d][n] directly from LDTM regs.
// ---------------------------------------------------------------------------
extern __shared__ char dynsmem[];

__global__ __launch_bounds__(256, 1) void qkv_gemm(const float* __restrict__ bias) {
#if USE_TC
    const int tid = threadIdx.x, wid = tid >> 5, lane = tid & 31;
    const int cid = blockIdx.x;
    const int bm = (cid >> 2) * TBM;
    const int bn0 = (cid & 3) * (NTILES * TBN);

    uint32_t sb_raw = (uint32_t)__cvta_generic_to_shared(dynsmem);
    uint32_t s0 = (sb_raw + 1023) & ~1023u;
    uint32_t tilesA = s0 + 1024;
    uint32_t tilesB = tilesA + A_RING * A_TILE;

    if (tid == 0) {
        mbar_init(s0 + 8, 1);
        mbar_init(s0 + 16, 1);
        mbar_init(s0 + 24, 1);
        mbar_init(s0 + 32, 1);
    }
    if (wid == 0)
        asm volatile("tcgen05.alloc.cta_group::1.sync.aligned.shared::cta.b32 [%0], %1;"
                     :: "r"(s0), "r"(512u) : "memory");
    __syncthreads();
    uint32_t tmem;
    asm volatile("ld.shared.b32 %0, [%1];" : "=r"(tmem) : "r"(s0));

    auto issue_chunk = [&](int g) {
        const int tile = g / CPT;
        const int tt = g - tile * CPT;
        const int j = tt / 3, p = tt - 3 * j;
        const int bn = bn0 + tile * TBN;
        const int ja = j * CHUNK;
        if (p != 1) {
            const __nv_bfloat16* ag =
                ((p == 0) ? g_Xh : g_Xl) + (size_t)bm * K_DIM + ja;
            const uint32_t dst = tilesA + ((2 * j + (p == 2 ? 1 : 0)) % A_RING) * A_TILE;
#pragma unroll
            for (int i = 0; i < 8; i++) {
                int idx = tid + i * 256;
                int r = idx >> 3, s = idx & 7;
                cp16s(dst + (r << 7) + ((s ^ (r & 7)) << 4),
                      ag + (size_t)r * K_DIM + s * 8);
            }
        }
        if (p != 2) {
            const __nv_bfloat16* bg =
                ((p == 0) ? g_Wh : g_Wl) + (size_t)bn * K_DIM + ja;
            const uint32_t dst = tilesB + ((2 * j + (p == 1 ? 1 : 0)) % B_RING) * B_TILE;
#pragma unroll
            for (int i = 0; i < 8; i++) {
                int idx = tid + i * 256;
                int r = idx >> 3, s = idx & 7;
                cp16s(dst + (r << 7) + ((s ^ (r & 7)) << 4),
                      bg + (size_t)r * K_DIM + s * 8);
            }
        }
        asm volatile("cp.async.commit_group;" ::: "memory");
    };

    issue_chunk(0);
    issue_chunk(1);

    for (int tile = 0; tile < NTILES; tile++) {
        const int gbase = tile * CPT;
        const int bn = bn0 + tile * TBN;

        for (int t = 0; t < CPT; t++) {
            if (t < CPT - 1)
                asm volatile("cp.async.wait_group 1;" ::: "memory");
            else
                asm volatile("cp.async.wait_group 0;" ::: "memory");
            __syncthreads();

            if (wid == 0 && elect_one_pred()) {
                asm volatile("fence.proxy.async.shared::cta;" ::: "memory");
                const int j = t / 3, p = t - 3 * j;
                const uint32_t aslot = (2 * j + (p == 2 ? 1 : 0)) % A_RING;
                const uint32_t bslot = (2 * j + (p == 1 ? 1 : 0)) % B_RING;
                const uint32_t ab = tilesA + aslot * A_TILE;
                const uint32_t bb = tilesB + bslot * B_TILE;
                uint64_t a0 = make_desc(ab);
                uint64_t a1 = make_desc(ab + 16384);
                uint64_t bd = make_desc(bb);
#pragma unroll
                for (int k = 0; k < 4; k++) {
                    uint32_t en = (t > 0 || k > 0) ? 1u : 0u;
                    mma_f16_ss(tmem,       a0 + k * 2, bd + k * 2, IDESC_BF16, en);
                    mma_f16_ss(tmem + 256, a1 + k * 2, bd + k * 2, IDESC_BF16, en);
                }
                tc_commit(s0 + 8 + 8 * ((gbase + t) % 3));
            }

            const int c = t + 2;
            if (c < CPT) {
                const int g = gbase + c;
                if (g >= 4) {
                    const int cc = g - 4;
                    mbar_wait(s0 + 8 + 8 * (cc % 3), (uint32_t)((cc / 3) & 1));
                }
                issue_chunk(g);
            }
        }

        if (wid == 0 && elect_one_pred()) tc_commit(s0 + 32);
        mbar_wait(s0 + 32, (uint32_t)(tile & 1));
        asm volatile("tcgen05.fence::after_thread_sync;" ::: "memory");

        if (tile + 1 < NTILES) {
            issue_chunk(gbase + CPT);
            issue_chunk(gbase + CPT + 1);
        }

        // ---- epilogue ----
        {
            const int half = wid >> 2;
            const int m = bm + half * 128 + (wid & 3) * 32 + lane;
            const int b = m >> 11;
            const int nrow0 = (bm & 2047) + half * 128 + (wid & 3) * 32;
            const int nidx = nrow0 + lane;
            float* epi = (float*)(dynsmem + (s0 - sb_raw) + 1024 + A_TILE) +
                         wid * (32 * 33);

            for (int cb = 0; cb < 8; cb++) {
                uint32_t r[32];
                LDTM_X32(r, tmem + half * 256 + cb * 32);
                asm volatile("tcgen05.wait::ld.sync.aligned;" ::: "memory");

                // K/V: direct coalesced stores (reg j = column, lane = n)
#pragma unroll
                for (int j = 0; j < 32; j++) {
                    int jc = bn + cb * 32 + j;
                    int cc = jc % 3;
                    if (cc != 0) {
                        float bv = __ldg(&bias[jc]);
                        int hdv = jc / 3;
                        int d = hdv & 63, h = hdv >> 6;
                        float* dst = (cc == 1) ? g_Kt : g_Vt;
                        dst[(((size_t)((b << 4) + h)) * HD + d) * SEQ + nidx] =
                            __uint_as_float(r[j]) + bv;
                    }
                }

                // Q: smem transpose then per-column scatter
                int jcl = bn + cb * 32 + lane;
                __syncwarp();
#pragma unroll
                for (int j = 0; j < 32; j++) epi[j * 33 + lane] = __uint_as_float(r[j]);
                __syncwarp();
                if (jcl % 3 == 0) {
                    float bv = bias[jcl];
                    int hdv = jcl / 3;
                    int d = hdv & 63, h = hdv >> 6;
                    size_t rowb = (size_t)((b << 4) + h) * SEQ;
#pragma unroll
                    for (int rj = 0; rj < 32; rj++) {
                        g_Q[(rowb + nrow0 + rj) * HD + d] = epi[lane * 33 + rj] + bv;
                    }
                }
                __syncwarp();
            }
            asm volatile("tcgen05.fence::before_thread_sync;" ::: "memory");
        }
        __syncthreads();
    }

    if (wid == 0) {
        asm volatile("tcgen05.relinquish_alloc_permit.cta_group::1.sync.aligned;");
        asm volatile("tcgen05.dealloc.cta_group::1.sync.aligned.b32 %0, %1;"
                     :: "r"(tmem), "r"(512u));
    }
#else
    // -------- fallback: mma.sync, 3 n-tiles x quadrants, 3 accumulate passes
    typedef __nv_bfloat16 RowA[128][GBK + APAD];
    RowA* As = (RowA*)dynsmem;
    RowA* Bs = (RowA*)(dynsmem + 2 * 128 * (GBK + APAD) * 2);

    const int tid = threadIdx.x;
    const int wid = tid >> 5, lane = tid & 31;
    const int wm = wid >> 2, wn = wid & 3;
    const int q = lane >> 3, rr = lane & 7;
    const int r2 = lane >> 2, c2 = lane & 3;
    const int cid = blockIdx.x;
    const int bm_base = (cid >> 2) * TBM;
    const int bn_base = (cid & 3) * (NTILES * TBN);

    const __nv_bfloat16* APASS[3] = {g_Xh, g_Xh, g_Xl};
    const __nv_bfloat16* BPASS[3] = {g_Wh, g_Wl, g_Wh};

    for (int tile = 0; tile < NTILES; tile++)
        for (int mq = 0; mq < 2; mq++)
            for (int nq = 0; nq < 2; nq++) {
                const int bm = bm_base + mq * 128;
                const int bn = bn_base + tile * TBN + nq * 128;

                float acc[4][4][4];
#pragma unroll
                for (int i = 0; i < 4; i++)
#pragma unroll
                    for (int j = 0; j < 4; j++)
#pragma unroll
                        for (int k = 0; k < 4; k++) acc[i][j][k] = 0.f;

                for (int pass = 0; pass < 3; pass++) {
                    const __nv_bfloat16* Ag = APASS[pass];
                    const __nv_bfloat16* Bg = BPASS[pass];
                    __syncthreads();

                    auto issue = [&](int t, int s) {
#pragma unroll
                        for (int it = 0; it < 2; it++) {
                            int idx = tid + it * 256;
                            int row = idx >> 2, seg = (idx & 3) << 3;
                            cp16s((uint32_t)__cvta_generic_to_shared(&As[s][row][seg]),
                                  &Ag[(size_t)(bm + row) * K_DIM + t * GBK + seg]);
                            cp16s((uint32_t)__cvta_generic_to_shared(&Bs[s][row][seg]),
                                  &Bg[(size_t)(bn + row) * K_DIM + t * GBK + seg]);
                        }
                        asm volatile("cp.async.commit_group;" ::: "memory");
                    };

                    issue(0, 0);
                    const int NIT = K_DIM / GBK;
                    for (int t = 0; t < NIT; t++) {
                        const int buf = t & 1;
                        asm volatile("cp.async.wait_group 0;" ::: "memory");
                        __syncthreads();
                        if (t + 1 < NIT) issue(t + 1, buf ^ 1);

#pragma unroll
                        for (int ks = 0; ks < 2; ks++) {
                            uint32_t a[4][4], bb[2][4];
#pragma unroll
                            for (int mf = 0; mf < 4; mf++) {
                                int arow = wm * 64 + mf * 16 + (q & 1) * 8 + rr;
                                int acol = ks * 16 + (q >> 1) * 8;
                                ldsm_x4(a[mf], &As[buf][arow][acol]);
                            }
#pragma unroll
                            for (int nh = 0; nh < 2; nh++) {
                                int brow = wn * 32 + nh * 16 + (q >> 1) * 8 + rr;
                                int bcol = ks * 16 + (q & 1) * 8;
                                ldsm_x4(bb[nh], &Bs[buf][brow][bcol]);
                            }
#pragma unroll
                            for (int mf = 0; mf < 4; mf++)
#pragma unroll
                                for (int nf = 0; nf < 4; nf++)
                                    mma_bf16(acc[mf][nf], a[mf], &bb[nf >> 1][(nf & 1) * 2]);
                        }
                        __syncthreads();
                    }
                }

#pragma unroll
                for (int nf = 0; nf < 4; nf++) {
#pragma unroll
                    for (int i1 = 0; i1 < 2; i1++) {
                        int jc = bn + wn * 32 + nf * 8 + c2 * 2 + i1;
                        float bv = __ldg(&bias[jc]);
                        int cc = jc % 3;
                        int hdv = jc / 3;
                        int d = hdv & 63, h = hdv >> 6;
#pragma unroll
                        for (int mf = 0; mf < 4; mf++)
#pragma unroll
                            for (int i2 = 0; i2 < 2; i2++) {
                                int m = bm + wm * 64 + mf * 16 + r2 + i2 * 8;
                                int b = m >> 11, n = m & 2047;
                                float val = acc[mf][nf][i2 * 2 + i1] + bv;
                                size_t bh16 = (size_t)((b << 4) + h);
                                if (cc == 0)
                                    g_Q[(bh16 * SEQ + n) * HD + d] = val;
                                else if (cc == 1)
                                    g_Kt[(bh16 * HD + d) * SEQ + n] = val;
                                else
                                    g_Vt[(bh16 * HD + d) * SEQ + n] = val;
                            }
                    }
                }
            }
#endif
}

// ---------------------------------------------------------------------------
// Stage 2: ktv_partial via mma.sync bf16 3-pass.
// grid (NSPLIT=8, BH). Per CTA: C[64 d1][64 d2] += over 256 n-rows.
// ---------------------------------------------------------------------------
__global__ __launch_bounds__(256) void ktv_partial() {
    const int sp = blockIdx.x, bh = blockIdx.y;
    const int tid = threadIdx.x, wid = tid >> 5, lane = tid & 31;
    const int q = lane >> 3, rr = lane & 7;
    const float* Ktp = g_Kt + (size_t)bh * HD * SEQ;
    const float* Vtp = g_Vt + (size_t)bh * HD * SEQ;
    const int nbase = sp * (SEQ / NSPLIT);          // 256 rows, 4 chunks of 64

    auto pl = [&](int buf, int w) -> __nv_bfloat16* {
        return (__nv_bfloat16*)(dynsmem + (size_t)(buf * 4 + w) * PLANE64);
    };

    float4 stg[8];
    auto ldg_chunk = [&](int c) {
        int n0 = nbase + c * 64;
#pragma unroll
        for (int i = 0; i < 4; i++) {
            int idx = tid + i * 256;
            int r = idx >> 4, c4 = (idx & 15) << 2;
            stg[i]     = *(const float4*)&Ktp[(size_t)r * SEQ + n0 + c4];
            stg[i + 4] = *(const float4*)&Vtp[(size_t)r * SEQ + n0 + c4];
        }
    };
    auto sts_chunk = [&](int buf) {
#pragma unroll
        for (int i = 0; i < 4; i++) {
            int idx = tid + i * 256;
            int r = idx >> 4, c4 = (idx & 15) << 2;
            uint32_t h0, l0, h1, l1;
            split2(stg[i].x, stg[i].y, h0, l0);
            split2(stg[i].z, stg[i].w, h1, l1);
            *(uint2*)&pl(buf, 0)[r * 72 + c4] = make_uint2(h0, h1);
            *(uint2*)&pl(buf, 1)[r * 72 + c4] = make_uint2(l0, l1);
            split2(stg[i + 4].x, stg[i + 4].y, h0, l0);
            split2(stg[i + 4].z, stg[i + 4].w, h1, l1);
            *(uint2*)&pl(buf, 2)[r * 72 + c4] = make_uint2(h0, h1);
            *(uint2*)&pl(buf, 3)[r * 72 + c4] = make_uint2(l0, l1);
        }
    };

    const int arow0 = (wid >> 1) * 16;
    const int bcol0 = (wid & 1) * 32;
    float acc[4][4] = {};

    ldg_chunk(0);
    sts_chunk(0);
    __syncthreads();

#pragma unroll
    for (int c = 0; c < 4; c++) {
        const int buf = c & 1;
        if (c + 1 < 4) ldg_chunk(c + 1);
        __nv_bfloat16 *Ah = pl(buf, 0), *Al = pl(buf, 1);
        __nv_bfloat16 *Bh = pl(buf, 2), *Bl = pl(buf, 3);
#pragma unroll
        for (int ks = 0; ks < 4; ks++) {
            uint32_t ah[4], al[4], bh2[2][4], bl2[2][4];
            ldsm_x4(ah, &Ah[(arow0 + (q & 1) * 8 + rr) * 72 + ks * 16 + (q >> 1) * 8]);
            ldsm_x4(al, &Al[(arow0 + (q & 1) * 8 + rr) * 72 + ks * 16 + (q >> 1) * 8]);
#pragma unroll
            for (int nh = 0; nh < 2; nh++) {
                ldsm_x4(bh2[nh], &Bh[(bcol0 + nh * 16 + (q >> 1) * 8 + rr) * 72 +
                                     ks * 16 + (q & 1) * 8]);
                ldsm_x4(bl2[nh], &Bl[(bcol0 + nh * 16 + (q >> 1) * 8 + rr) * 72 +
                                     ks * 16 + (q & 1) * 8]);
            }
#pragma unroll
            for (int nf = 0; nf < 4; nf++) {
                mma_bf16(acc[nf], ah, &bh2[nf >> 1][(nf & 1) * 2]);
                mma_bf16(acc[nf], ah, &bl2[nf >> 1][(nf & 1) * 2]);
                mma_bf16(acc[nf], al, &bh2[nf >> 1][(nf & 1) * 2]);
            }
        }
        if (c + 1 < 4) sts_chunk((c + 1) & 1);
        __syncthreads();
    }

    float* dst = g_KtVp + (size_t)(bh * NSPLIT + sp) * HD * HD;
    const int r2 = lane >> 2, c2 = lane & 3;
#pragma unroll
    for (int nf = 0; nf < 4; nf++) {
        int col = bcol0 + nf * 8 + c2 * 2;
        *(float2*)&dst[(arow0 + r2) * HD + col] = make_float2(acc[nf][0], acc[nf][1]);
        *(float2*)&dst[(arow0 + r2 + 8) * HD + col] = make_float2(acc[nf][2], acc[nf][3]);
    }
}

// ---------------------------------------------------------------------------
// Stage 3: reduce NSPLIT partials, fold in scale = 32. Output [e][d].
// ---------------------------------------------------------------------------
__global__ __launch_bounds__(256) void ktv_reduce() {
    int i = blockIdx.x * 256 + threadIdx.x;
    int bh = i >> 12, rc = i & 4095;
    float s = 0.f;
#pragma unroll
    for (int sp = 0; sp < NSPLIT; sp++)
        s += g_KtVp[(size_t)(bh * NSPLIT + sp) * 4096 + rc];
    g_KtV[i] = 32.0f * s;
}

// ---------------------------------------------------------------------------
// Stage 4: out = Q @ KtV via mma.sync bf16 3-pass.
// grid (SEQ/128, BH). Q tile 128x64 -> bf16 planes; KtV transposed to [d][e].
// ---------------------------------------------------------------------------
__global__ __launch_bounds__(256) void out_gemm(float* __restrict__ out) {
    const int bh = blockIdx.y;
    const int n0 = blockIdx.x * 128;
    const int tid = threadIdx.x, wid = tid >> 5, lane = tid & 31;
    const int q = lane >> 3, rr = lane & 7;

    __nv_bfloat16* Qh = (__nv_bfloat16*)dynsmem;
    __nv_bfloat16* Ql = (__nv_bfloat16*)(dynsmem + 18432);
    __nv_bfloat16* Bh = (__nv_bfloat16*)(dynsmem + 36864);
    __nv_bfloat16* Bl = (__nv_bfloat16*)(dynsmem + 46080);

#pragma unroll
    for (int i = 0; i < 8; i++) {
        int idx = tid + i * 256;
        int r = idx >> 4, c4 = (idx & 15) << 2;
        float4 v = *(const float4*)&g_Q[((size_t)bh * SEQ + n0 + r) * HD + c4];
        uint32_t h0, l0, h1, l1;
        split2(v.x, v.y, h0, l0);
        split2(v.z, v.w, h1, l1);
        *(uint2*)&Qh[r * 72 + c4] = make_uint2(h0, h1);
        *(uint2*)&Ql[r * 72 + c4] = make_uint2(l0, l1);
    }
#pragma unroll
    for (int i = 0; i < 4; i++) {
        int idx = tid + i * 256;
        int e = idx >> 4, d4 = (idx & 15) << 2;
        float4 v = *(const float4*)&g_KtV[((size_t)bh * HD + e) * HD + d4];
        float vv[4] = {v.x, v.y, v.z, v.w};
#pragma unroll
        for (int j2 = 0; j2 < 4; j2++) {
            __nv_bfloat16 hb = __float2bfloat16_rn(vv[j2]);
            __nv_bfloat16 lb = __float2bfloat16_rn(vv[j2] - __bfloat162float(hb));
            Bh[(d4 + j2) * 72 + e] = hb;
            Bl[(d4 + j2) * 72 + e] = lb;
        }
    }
    __syncthreads();

    const int arow0 = wid * 16;
    float acc[8][4] = {};
#pragma unroll
    for (int ks = 0; ks < 4; ks++) {
        uint32_t ah[4], al[4], bh2[4][4], bl2[4][4];
        ldsm_x4(ah, &Qh[(arow0 + (q & 1) * 8 + rr) * 72 + ks * 16 + (q >> 1) * 8]);
        ldsm_x4(al, &Ql[(arow0 + (q & 1) * 8 + rr) * 72 + ks * 16 + (q >> 1) * 8]);
#pragma unroll
        for (int nh = 0; nh < 4; nh++) {
            ldsm_x4(bh2[nh], &Bh[(nh * 16 + (q >> 1) * 8 + rr) * 72 +
                                 ks * 16 + (q & 1) * 8]);
            ldsm_x4(bl2[nh], &Bl[(nh * 16 + (q >> 1) * 8 + rr) * 72 +
                                 ks * 16 + (q & 1) * 8]);
        }
#pragma unroll
        for (int nf = 0; nf < 8; nf++) {
            mma_bf16(acc[nf], ah, &bh2[nf >> 1][(nf & 1) * 2]);
            mma_bf16(acc[nf], ah, &bl2[nf >> 1][(nf & 1) * 2]);
            mma_bf16(acc[nf], al, &bh2[nf >> 1][(nf & 1) * 2]);
        }
    }

    const int r2 = lane >> 2, c2 = lane & 3;
    size_t rowb = (size_t)bh * SEQ + n0 + arow0;
#pragma unroll
    for (int nf = 0; nf < 8; nf++) {
        int col = nf * 8 + c2 * 2;
        *(float2*)&out[(rowb + r2) * HD + col] = make_float2(acc[nf][0], acc[nf][1]);
        *(float2*)&out[(rowb + r2 + 8) * HD + col] = make_float2(acc[nf][2], acc[nf][3]);
    }
}

// ---------------------------------------------------------------------------
extern "C" void kernel_launch(void* const* d_in, const int* in_sizes, int n_in,
                              void* d_out, int out_size) {
    const float* x = (const float*)d_in[0];   // [4,2048,1024]
    const float* W = (const float*)d_in[1];   // [1024,3072]
    const float* b = (const float*)d_in[2];   // [3072]
    float* out = (float*)d_out;               // [4,16,2048,64]

    cudaFuncSetAttribute(qkv_gemm, cudaFuncAttributeMaxDynamicSharedMemorySize,
                         QKV_SMEM);
    cudaFuncSetAttribute(ktv_partial, cudaFuncAttributeMaxDynamicSharedMemorySize,
                         KTV_SMEM);
    cudaFuncSetAttribute(out_gemm, cudaFuncAttributeMaxDynamicSharedMemorySize,
                         OUT_SMEM);

    split_x<<<(M_TOT * K_DIM) / 1024, 256>>>(x);
    split_w<<<dim3(K_DIM / 32, N_TOT / 32), 256>>>(W);
    qkv_gemm<<<128, 256, QKV_SMEM>>>(b);
    ktv_partial<<<dim3(NSPLIT, BH), 256, KTV_SMEM>>>();
    ktv_reduce<<<(BH * HD * HD) / 256, 256>>>();
    out_gemm<<<dim3(SEQ / 128, BH), 256, OUT_SMEM>>>(out);
}